// round 14
// baseline (speedup 1.0000x reference)
#include <cuda_runtime.h>
#include <cuda_fp16.h>
#include <cstdint>

#define NB 4096
#define N2 8192
#define DD 256
#define INV_TEMP 2.0f
#define EX2_SCALE 2.885390081777927f   // 2 * log2(e)

#define BM 128
#define BN 128
#define BK 64
#define NCHUNK (DD / BK)         // 4 k-chunks
#define NSTRIPE (N2 / BN)        // 64 column stripes
#define NTILE 64
#define NTRI (NTILE * (NTILE + 1) / 2)   // 2080
#define PADK 72                  // f16 elems per smem row (144B)
#define NPERS 444                // persistent CTAs = 148 SMs x 3

// smem: 2 bufs x (A + B) chunks, then 2KB reduction scratch
#define CHUNK_ELEMS (BM * PADK)
#define BUFS_BYTES  (2 * 2 * CHUNK_ELEMS * 2)   // 73728
#define RED_OFF     BUFS_BYTES
#define SMEM_TOTAL  (BUFS_BYTES + 2048)         // 75776 -> 3 CTAs/SM

// Scratch (static device globals — no allocation)
__device__ __half         g_zh[(size_t)N2 * DD];            // normalized rows fp16
__device__ float          g_partial[(size_t)NSTRIPE * N2];  // [stripe][row]
__device__ float          g_pos[N2];
__device__ float          g_loss[N2];
__device__ int            g_sem;

__device__ __forceinline__ uint32_t smem_u32(const void* p) {
    return (uint32_t)__cvta_generic_to_shared(p);
}
__device__ __forceinline__ void ldsm_x4(uint32_t addr, uint32_t& r0, uint32_t& r1,
                                        uint32_t& r2, uint32_t& r3) {
    asm volatile("ldmatrix.sync.aligned.m8n8.x4.shared.b16 {%0,%1,%2,%3}, [%4];"
                 : "=r"(r0), "=r"(r1), "=r"(r2), "=r"(r3) : "r"(addr));
}
__device__ __forceinline__ void mma_f16acc(uint32_t* d, const uint32_t* a, const uint32_t* b) {
    asm volatile(
        "mma.sync.aligned.m16n8k16.row.col.f16.f16.f16.f16 "
        "{%0,%1}, {%2,%3,%4,%5}, {%6,%7}, {%0,%1};"
        : "+r"(d[0]), "+r"(d[1])
        : "r"(a[0]), "r"(a[1]), "r"(a[2]), "r"(a[3]), "r"(b[0]), "r"(b[1]));
}
__device__ __forceinline__ uint32_t h2ex2(uint32_t x) {
    uint32_t y;
    asm("ex2.approx.f16x2 %0, %1;" : "=r"(y) : "r"(x));
    return y;
}
__device__ __forceinline__ uint32_t h2mul(uint32_t a, uint32_t b) {
    __half2 r = __hmul2(*(__half2*)&a, *(__half2*)&b);
    return *(uint32_t*)&r;
}
__device__ __forceinline__ uint32_t h2add(uint32_t a, uint32_t b) {
    __half2 r = __hadd2(*(__half2*)&a, *(__half2*)&b);
    return *(uint32_t*)&r;
}
__device__ __forceinline__ void cp_async16(uint32_t smem_addr, const void* gptr) {
    asm volatile("cp.async.cg.shared.global [%0], [%1], 16;"
                 :: "r"(smem_addr), "l"(gptr) : "memory");
}
#define CP_COMMIT() asm volatile("cp.async.commit_group;" ::: "memory")
#define CP_WAIT(n)  asm volatile("cp.async.wait_group %0;" :: "n"(n) : "memory")

__device__ __forceinline__ void tri_decode(int idx, int& bi, int& bj) {
    bi = (int)(64.5f - sqrtf(64.5f * 64.5f - 2.0f * (float)idx));
    while ((bi + 1) * NTILE - ((bi + 1) * bi) / 2 <= idx) ++bi;
    while (bi * NTILE - (bi * (bi - 1)) / 2 > idx) --bi;
    bj = bi + (idx - (bi * NTILE - (bi * (bi - 1)) / 2));
}

// ---------------------------------------------------------------------------
// Kernel 1: L2-normalize. One warp handles rows (w, w+NB).
// ---------------------------------------------------------------------------
__global__ void k_normalize(const float* __restrict__ xi, const float* __restrict__ xj) {
    int w    = blockIdx.x * 8 + (threadIdx.x >> 5);
    int lane = threadIdx.x & 31;
    const float* sa = xi + (size_t)w * DD;
    const float* sb = xj + (size_t)w * DD;
    float4 a0 = *(const float4*)(sa + lane * 4);
    float4 a1 = *(const float4*)(sa + 128 + lane * 4);
    float4 b0 = *(const float4*)(sb + lane * 4);
    float4 b1 = *(const float4*)(sb + 128 + lane * 4);
    float s_a = a0.x*a0.x + a0.y*a0.y + a0.z*a0.z + a0.w*a0.w
              + a1.x*a1.x + a1.y*a1.y + a1.z*a1.z + a1.w*a1.w;
    float s_b = b0.x*b0.x + b0.y*b0.y + b0.z*b0.z + b0.w*b0.w
              + b1.x*b1.x + b1.y*b1.y + b1.z*b1.z + b1.w*b1.w;
    #pragma unroll
    for (int o = 16; o > 0; o >>= 1) {
        s_a += __shfl_xor_sync(0xffffffffu, s_a, o);
        s_b += __shfl_xor_sync(0xffffffffu, s_b, o);
    }
    float ia = 1.0f / fmaxf(sqrtf(s_a), 1e-12f);
    float ib = 1.0f / fmaxf(sqrtf(s_b), 1e-12f);

    __half2 h[4];
    h[0] = __floats2half2_rn(a0.x * ia, a0.y * ia);
    h[1] = __floats2half2_rn(a0.z * ia, a0.w * ia);
    h[2] = __floats2half2_rn(a1.x * ia, a1.y * ia);
    h[3] = __floats2half2_rn(a1.z * ia, a1.w * ia);
    __half* da = g_zh + (size_t)w * DD;
    *(uint2*)(da + lane * 4)       = make_uint2(*(uint32_t*)&h[0], *(uint32_t*)&h[1]);
    *(uint2*)(da + 128 + lane * 4) = make_uint2(*(uint32_t*)&h[2], *(uint32_t*)&h[3]);

    h[0] = __floats2half2_rn(b0.x * ib, b0.y * ib);
    h[1] = __floats2half2_rn(b0.z * ib, b0.w * ib);
    h[2] = __floats2half2_rn(b1.x * ib, b1.y * ib);
    h[3] = __floats2half2_rn(b1.z * ib, b1.w * ib);
    __half* db = g_zh + (size_t)(w + NB) * DD;
    *(uint2*)(db + lane * 4)       = make_uint2(*(uint32_t*)&h[0], *(uint32_t*)&h[1]);
    *(uint2*)(db + 128 + lane * 4) = make_uint2(*(uint32_t*)&h[2], *(uint32_t*)&h[3]);
}

// ---------------------------------------------------------------------------
// Kernel 2: persistent f16-acc HMMA. 444 CTAs loop over the 2080 upper-
// triangle 128x128 tiles; next tile's first chunk prefetched across the
// epilogue (continuous double-buffer parity chain).
// ---------------------------------------------------------------------------
__global__ __launch_bounds__(128, 3) void k_expsum_mma() {
    extern __shared__ char smem[];
    int tid   = threadIdx.x;
    int lane  = tid & 31;
    int wid   = tid >> 5;
    int warpM = wid >> 1;
    int warpN = wid & 1;

    uint32_t sbase = smem_u32(smem);
    int lrow = tid >> 3;              // 0..15
    int lcol = (tid & 7) * 8;

    int nb = 0;   // chunks issued (parity chain)
    auto load_chunk = [&](int r0, int c0, int kc) {
        uint32_t aoff = sbase + (uint32_t)((nb & 1) * 2 * CHUNK_ELEMS) * 2;
        uint32_t boff = aoff + (uint32_t)CHUNK_ELEMS * 2;
        const __half* gA = g_zh + (size_t)r0 * DD + kc * BK;
        const __half* gB = g_zh + (size_t)c0 * DD + kc * BK;
        #pragma unroll
        for (int i = 0; i < 8; ++i) {
            int row = lrow + i * 16;
            cp_async16(aoff + (uint32_t)(row * PADK + lcol) * 2,
                       gA + (size_t)row * DD + lcol);
            cp_async16(boff + (uint32_t)(row * PADK + lcol) * 2,
                       gB + (size_t)row * DD + lcol);
        }
        ++nb;
        CP_COMMIT();
    };

    uint32_t aLane[4], bLane[4];
    {
        int arow_lane = lane & 15;
        int akh       = lane >> 4;
        #pragma unroll
        for (int m = 0; m < 4; ++m) {
            int row = warpM * 64 + m * 16 + arow_lane;
            aLane[m] = (uint32_t)(row * PADK + akh * 8) * 2;
        }
        int bn  = (lane & 7) | ((lane >> 4) << 3);
        int bkh = (lane >> 3) & 1;
        #pragma unroll
        for (int q = 0; q < 4; ++q) {
            int n = warpN * 64 + q * 16 + bn;
            bLane[q] = (uint32_t)(n * PADK + bkh * 8) * 2;
        }
    }

    int r_base = warpM * 64 + (lane >> 2);
    int c_base = warpN * 64 + (lane & 3) * 2;
    const __half2 cmulh = __float2half2_rn(EX2_SCALE);
    uint32_t cmul_u = *(const uint32_t*)&cmulh;
    float* rowred = (float*)(smem + RED_OFF);          // [128][2]
    float* colred = (float*)(smem + RED_OFF) + 256;    // [128][2]

    int idx = blockIdx.x;
    int bi, bj;
    tri_decode(idx, bi, bj);
    load_chunk(bi * BM, bj * BN, 0);
    int consumed = 0;

    while (true) {
        int r0 = bi * BM;
        int c0 = bj * BN;
        int nidx = idx + NPERS;
        bool hasNext = (nidx < NTRI);
        int nbi = 0, nbj = 0;
        if (hasNext) tri_decode(nidx, nbi, nbj);

        uint32_t acc[4][8][2];
        #pragma unroll
        for (int m = 0; m < 4; ++m)
            #pragma unroll
            for (int q = 0; q < 8; ++q) { acc[m][q][0] = 0u; acc[m][q][1] = 0u; }

        for (int kc = 0; kc < NCHUNK; ++kc) {
            if (kc < 3)        { load_chunk(r0, c0, kc + 1); CP_WAIT(1); }
            else if (hasNext)  { load_chunk(nbi * BM, nbj * BN, 0); CP_WAIT(1); }
            else               { CP_WAIT(0); }
            __syncthreads();

            uint32_t abuf = sbase + (uint32_t)((consumed & 1) * 2 * CHUNK_ELEMS) * 2;
            uint32_t bbuf = abuf + (uint32_t)CHUNK_ELEMS * 2;
            ++consumed;

            #pragma unroll
            for (int ks = 0; ks < BK / 16; ++ks) {
                uint32_t a[4][4];
                #pragma unroll
                for (int m = 0; m < 4; ++m)
                    ldsm_x4(abuf + aLane[m] + ks * 32, a[m][0], a[m][1], a[m][2], a[m][3]);
                uint32_t b[8][2];
                #pragma unroll
                for (int q = 0; q < 4; ++q)
                    ldsm_x4(bbuf + bLane[q] + ks * 32,
                            b[2*q][0], b[2*q][1], b[2*q+1][0], b[2*q+1][1]);
                #pragma unroll
                for (int m = 0; m < 4; ++m)
                    #pragma unroll
                    for (int q = 0; q < 8; ++q)
                        mma_f16acc(acc[m][q], a[m], b[q]);
            }
            __syncthreads();
        }

        // --- positive pairs ---
        if (bj == bi + 32) {
            #pragma unroll
            for (int m = 0; m < 4; ++m)
                #pragma unroll
                for (int q = 0; q < 8; ++q) {
                    float2 lo = __half22float2(*(__half2*)&acc[m][q][0]);
                    float2 hi = __half22float2(*(__half2*)&acc[m][q][1]);
                    int rl0 = r_base + m * 16, cl = c_base + q * 8;
                    if (rl0 == cl)         { g_pos[r0 + rl0] = lo.x;     g_pos[r0 + rl0 + NB] = lo.x; }
                    if (rl0 == cl + 1)     { g_pos[r0 + rl0] = lo.y;     g_pos[r0 + rl0 + NB] = lo.y; }
                    if (rl0 + 8 == cl)     { g_pos[r0 + rl0 + 8] = hi.x; g_pos[r0 + rl0 + 8 + NB] = hi.x; }
                    if (rl0 + 8 == cl + 1) { g_pos[r0 + rl0 + 8] = hi.y; g_pos[r0 + rl0 + 8 + NB] = hi.y; }
                }
        }

        // --- exp (f16x2) + HADD2 partial sums ---
        bool isDiag = (bi == bj);
        uint32_t racc0[4], racc1[4], cacc[8];
        #pragma unroll
        for (int m = 0; m < 4; ++m) { racc0[m] = 0u; racc1[m] = 0u; }
        #pragma unroll
        for (int q = 0; q < 8; ++q) cacc[q] = 0u;

        #pragma unroll
        for (int m = 0; m < 4; ++m)
            #pragma unroll
            for (int q = 0; q < 8; ++q) {
                uint32_t e0u = h2ex2(h2mul(acc[m][q][0], cmul_u));
                uint32_t e1u = h2ex2(h2mul(acc[m][q][1], cmul_u));
                if (isDiag) {
                    int rl0 = r_base + m * 16, cl = c_base + q * 8;
                    if (rl0 == cl)         e0u &= 0xFFFF0000u;
                    if (rl0 == cl + 1)     e0u &= 0x0000FFFFu;
                    if (rl0 + 8 == cl)     e1u &= 0xFFFF0000u;
                    if (rl0 + 8 == cl + 1) e1u &= 0x0000FFFFu;
                }
                racc0[m] = h2add(racc0[m], e0u);
                racc1[m] = h2add(racc1[m], e1u);
                cacc[q]  = h2add(cacc[q], h2add(e0u, e1u));
            }

        #pragma unroll
        for (int m = 0; m < 4; ++m) {
            float2 f0 = __half22float2(*(__half2*)&racc0[m]);
            float2 f1 = __half22float2(*(__half2*)&racc1[m]);
            float a0 = f0.x + f0.y;
            float a1 = f1.x + f1.y;
            a0 += __shfl_xor_sync(0xffffffffu, a0, 1);
            a0 += __shfl_xor_sync(0xffffffffu, a0, 2);
            a1 += __shfl_xor_sync(0xffffffffu, a1, 1);
            a1 += __shfl_xor_sync(0xffffffffu, a1, 2);
            if ((lane & 3) == 0) {
                int row = warpM * 64 + m * 16 + (lane >> 2);
                rowred[row * 2 + warpN]       = a0;
                rowred[(row + 8) * 2 + warpN] = a1;
            }
        }

        if (!isDiag) {
            #pragma unroll
            for (int q = 0; q < 8; ++q) {
                float2 fc = __half22float2(*(__half2*)&cacc[q]);
                float a0 = fc.x, a1 = fc.y;
                a0 += __shfl_xor_sync(0xffffffffu, a0, 4);
                a0 += __shfl_xor_sync(0xffffffffu, a0, 8);
                a0 += __shfl_xor_sync(0xffffffffu, a0, 16);
                a1 += __shfl_xor_sync(0xffffffffu, a1, 4);
                a1 += __shfl_xor_sync(0xffffffffu, a1, 8);
                a1 += __shfl_xor_sync(0xffffffffu, a1, 16);
                if (lane < 4) {
                    int n = warpN * 64 + q * 8 + lane * 2;
                    colred[n * 2 + warpM]       = a0;
                    colred[(n + 1) * 2 + warpM] = a1;
                }
            }
        }
        __syncthreads();

        g_partial[(size_t)bj * N2 + r0 + tid] = rowred[tid * 2] + rowred[tid * 2 + 1];
        if (!isDiag)
            g_partial[(size_t)bi * N2 + c0 + tid] = colred[tid * 2] + colred[tid * 2 + 1];

        if (!hasNext) break;
        __syncthreads();     // red region reused next tile
        idx = nidx; bi = nbi; bj = nbj;
    }
}

// ---------------------------------------------------------------------------
// Kernel 3: per-row loss + fused mean.
// ---------------------------------------------------------------------------
__global__ void k_rowloss(float* __restrict__ out) {
    __shared__ float st[8][68];
    __shared__ float sm[256];
    __shared__ int isLast;
    int tid = threadIdx.x;
    int r0  = blockIdx.x * 8;

    {
        int s  = tid >> 2;
        int ro = (tid & 3) * 2;
        float2 v = *(const float2*)&g_partial[(size_t)s * N2 + r0 + ro];
        st[ro][s]     = v.x;
        st[ro + 1][s] = v.y;
    }
    __syncthreads();

    int w    = tid >> 5;
    int lane = tid & 31;
    float S = st[w][lane] + st[w][lane + 32];
    #pragma unroll
    for (int o = 16; o > 0; o >>= 1) S += __shfl_xor_sync(0xffffffffu, S, o);

    if (lane == 0) {
        float ep = __expf(INV_TEMP * g_pos[r0 + w]);
        g_loss[r0 + w] = -logf(ep / (ep + S));
    }
    __threadfence();
    __syncthreads();
    if (tid == 0) {
        int old = atomicAdd(&g_sem, 1);
        isLast = (old == gridDim.x - 1);
    }
    __syncthreads();
    if (isLast) {
        float s = 0.f;
        #pragma unroll
        for (int i = 0; i < 8; ++i) {
            float4 v = *(const float4*)&g_loss[(tid + i * 256) * 4];
            s += v.x + v.y + v.z + v.w;
        }
        sm[tid] = s;
        __syncthreads();
        for (int stp = 128; stp > 0; stp >>= 1) {
            if (tid < stp) sm[tid] += sm[tid + stp];
            __syncthreads();
        }
        if (tid == 0) { out[0] = sm[0] * (1.0f / (float)N2); g_sem = 0; }
    }
}

extern "C" void kernel_launch(void* const* d_in, const int* in_sizes, int n_in,
                              void* d_out, int out_size) {
    const float* xi = (const float*)d_in[0];
    const float* xj = (const float*)d_in[1];
    float* out = (float*)d_out;

    cudaFuncSetAttribute(k_expsum_mma, cudaFuncAttributeMaxDynamicSharedMemorySize, SMEM_TOTAL);

    k_normalize<<<512, 256>>>(xi, xj);
    k_expsum_mma<<<NPERS, 128, SMEM_TOTAL>>>();
    k_rowloss<<<N2 / 8, 256>>>(out);
}

// round 15
// speedup vs baseline: 1.1315x; 1.1315x over previous
#include <cuda_runtime.h>
#include <cuda_fp16.h>
#include <cstdint>

#define NB 4096
#define N2 8192
#define DD 256
#define INV_TEMP 2.0f
#define EX2_SCALE 2.885390081777927f   // 2 * log2(e)

#define BM 128
#define BN 128
#define BK 64
#define NCHUNK (DD / BK)         // 4 k-chunks
#define NSTRIPE (N2 / BN)        // 64 column stripes
#define NTILE 64
#define NTRI (NTILE * (NTILE + 1) / 2)   // 2080
#define PADK 72                  // f16 elems per smem row (144B)

// Scratch (static device globals — no allocation)
__device__ __half         g_zh[(size_t)N2 * DD];            // normalized rows fp16
__device__ float          g_partial[(size_t)NSTRIPE * N2];  // [stripe][row]
__device__ float          g_pos[N2];
__device__ float          g_loss[N2];
__device__ int            g_sem;

__device__ __forceinline__ uint32_t smem_u32(const void* p) {
    return (uint32_t)__cvta_generic_to_shared(p);
}
__device__ __forceinline__ void ldsm_x4(uint32_t addr, uint32_t& r0, uint32_t& r1,
                                        uint32_t& r2, uint32_t& r3) {
    asm volatile("ldmatrix.sync.aligned.m8n8.x4.shared.b16 {%0,%1,%2,%3}, [%4];"
                 : "=r"(r0), "=r"(r1), "=r"(r2), "=r"(r3) : "r"(addr));
}
__device__ __forceinline__ void mma_f16acc(uint32_t* d, const uint32_t* a, const uint32_t* b) {
    asm volatile(
        "mma.sync.aligned.m16n8k16.row.col.f16.f16.f16.f16 "
        "{%0,%1}, {%2,%3,%4,%5}, {%6,%7}, {%0,%1};"
        : "+r"(d[0]), "+r"(d[1])
        : "r"(a[0]), "r"(a[1]), "r"(a[2]), "r"(a[3]), "r"(b[0]), "r"(b[1]));
}
__device__ __forceinline__ uint32_t h2ex2(uint32_t x) {
    uint32_t y;
    asm("ex2.approx.f16x2 %0, %1;" : "=r"(y) : "r"(x));
    return y;
}
__device__ __forceinline__ uint32_t h2mul(uint32_t a, uint32_t b) {
    __half2 r = __hmul2(*(__half2*)&a, *(__half2*)&b);
    return *(uint32_t*)&r;
}
__device__ __forceinline__ uint32_t h2add(uint32_t a, uint32_t b) {
    __half2 r = __hadd2(*(__half2*)&a, *(__half2*)&b);
    return *(uint32_t*)&r;
}
__device__ __forceinline__ void cp_async16(uint32_t smem_addr, const void* gptr) {
    asm volatile("cp.async.cg.shared.global [%0], [%1], 16;"
                 :: "r"(smem_addr), "l"(gptr) : "memory");
}
#define CP_COMMIT() asm volatile("cp.async.commit_group;" ::: "memory")
#define CP_WAIT(n)  asm volatile("cp.async.wait_group %0;" :: "n"(n) : "memory")

// ---------------------------------------------------------------------------
// Kernel 1: L2-normalize. One warp handles TWO pairs (4 rows): p, p+NB,
// p+2048, p+2048+NB. 8 independent 16B loads in flight per thread.
// ---------------------------------------------------------------------------
__global__ void k_normalize(const float* __restrict__ xi, const float* __restrict__ xj) {
    int p    = blockIdx.x * 8 + (threadIdx.x >> 5);   // 0..2047
    int lane = threadIdx.x & 31;
    const float* s0 = xi + (size_t)p * DD;
    const float* s1 = xj + (size_t)p * DD;
    const float* s2 = xi + (size_t)(p + 2048) * DD;
    const float* s3 = xj + (size_t)(p + 2048) * DD;

    float4 v[4][2];
    v[0][0] = *(const float4*)(s0 + lane * 4);
    v[1][0] = *(const float4*)(s1 + lane * 4);
    v[2][0] = *(const float4*)(s2 + lane * 4);
    v[3][0] = *(const float4*)(s3 + lane * 4);
    v[0][1] = *(const float4*)(s0 + 128 + lane * 4);
    v[1][1] = *(const float4*)(s1 + 128 + lane * 4);
    v[2][1] = *(const float4*)(s2 + 128 + lane * 4);
    v[3][1] = *(const float4*)(s3 + 128 + lane * 4);

    float s[4];
    #pragma unroll
    for (int r = 0; r < 4; ++r) {
        float4 a = v[r][0], b = v[r][1];
        s[r] = a.x*a.x + a.y*a.y + a.z*a.z + a.w*a.w
             + b.x*b.x + b.y*b.y + b.z*b.z + b.w*b.w;
    }
    #pragma unroll
    for (int o = 16; o > 0; o >>= 1) {
        #pragma unroll
        for (int r = 0; r < 4; ++r)
            s[r] += __shfl_xor_sync(0xffffffffu, s[r], o);
    }
    int rows[4] = {p, p + NB, p + 2048, p + 2048 + NB};
    #pragma unroll
    for (int r = 0; r < 4; ++r) {
        float inv = 1.0f / fmaxf(sqrtf(s[r]), 1e-12f);
        float4 a = v[r][0], b = v[r][1];
        __half2 h[4];
        h[0] = __floats2half2_rn(a.x * inv, a.y * inv);
        h[1] = __floats2half2_rn(a.z * inv, a.w * inv);
        h[2] = __floats2half2_rn(b.x * inv, b.y * inv);
        h[3] = __floats2half2_rn(b.z * inv, b.w * inv);
        __half* d = g_zh + (size_t)rows[r] * DD;
        *(uint2*)(d + lane * 4)       = make_uint2(*(uint32_t*)&h[0], *(uint32_t*)&h[1]);
        *(uint2*)(d + 128 + lane * 4) = make_uint2(*(uint32_t*)&h[2], *(uint32_t*)&h[3]);
    }
}

// ---------------------------------------------------------------------------
// Kernel 2: f16-acc HMMA 128x128 tile, upper triangle, 4 warps x (64x64).
// (Exact R11 configuration: 2080 CTAs, 128 threads, 3 CTAs/SM.)
// ---------------------------------------------------------------------------
#define CHUNK_ELEMS (BM * PADK)
#define SMEM_BYTES  (2 * 2 * CHUNK_ELEMS * 2)   // 73728 B

__global__ __launch_bounds__(128, 3) void k_expsum_mma() {
    extern __shared__ __half smem[];
    int tid   = threadIdx.x;
    int lane  = tid & 31;
    int wid   = tid >> 5;
    int warpM = wid >> 1;
    int warpN = wid & 1;

    int idx = blockIdx.x;
    int bi = (int)(64.5f - sqrtf(64.5f * 64.5f - 2.0f * (float)idx));
    while ((bi + 1) * NTILE - ((bi + 1) * bi) / 2 <= idx) ++bi;
    while (bi * NTILE - (bi * (bi - 1)) / 2 > idx) --bi;
    int bj = bi + (idx - (bi * NTILE - (bi * (bi - 1)) / 2));
    int r0 = bi * BM;
    int c0 = bj * BN;

    int lrow = tid >> 3;
    int lcol = (tid & 7) * 8;
    uint32_t sbase = smem_u32(smem);

    auto load_chunk = [&](int kc, int b) {
        uint32_t aoff = sbase + (uint32_t)(b * 2 * CHUNK_ELEMS) * 2;
        uint32_t boff = aoff + (uint32_t)CHUNK_ELEMS * 2;
        const __half* gA = g_zh + (size_t)r0 * DD + kc * BK;
        const __half* gB = g_zh + (size_t)c0 * DD + kc * BK;
        #pragma unroll
        for (int i = 0; i < 8; ++i) {
            int row = lrow + i * 16;
            cp_async16(aoff + (uint32_t)(row * PADK + lcol) * 2,
                       gA + (size_t)row * DD + lcol);
            cp_async16(boff + (uint32_t)(row * PADK + lcol) * 2,
                       gB + (size_t)row * DD + lcol);
        }
        CP_COMMIT();
    };

    uint32_t aLane[4], bLane[4];
    {
        int arow_lane = lane & 15;
        int akh       = lane >> 4;
        #pragma unroll
        for (int m = 0; m < 4; ++m) {
            int row = warpM * 64 + m * 16 + arow_lane;
            aLane[m] = (uint32_t)(row * PADK + akh * 8) * 2;
        }
        int bn  = (lane & 7) | ((lane >> 4) << 3);
        int bkh = (lane >> 3) & 1;
        #pragma unroll
        for (int q = 0; q < 4; ++q) {
            int n = warpN * 64 + q * 16 + bn;
            bLane[q] = (uint32_t)(n * PADK + bkh * 8) * 2;
        }
    }

    uint32_t acc[4][8][2];
    #pragma unroll
    for (int m = 0; m < 4; ++m)
        #pragma unroll
        for (int q = 0; q < 8; ++q) { acc[m][q][0] = 0u; acc[m][q][1] = 0u; }

    load_chunk(0, 0);

    #pragma unroll
    for (int kc = 0; kc < NCHUNK; ++kc) {
        if (kc + 1 < NCHUNK) { load_chunk(kc + 1, (kc + 1) & 1); CP_WAIT(1); }
        else                 { CP_WAIT(0); }
        __syncthreads();

        uint32_t abuf = sbase + (uint32_t)((kc & 1) * 2 * CHUNK_ELEMS) * 2;
        uint32_t bbuf = abuf + (uint32_t)CHUNK_ELEMS * 2;

        #pragma unroll
        for (int ks = 0; ks < BK / 16; ++ks) {
            uint32_t a[4][4];
            #pragma unroll
            for (int m = 0; m < 4; ++m)
                ldsm_x4(abuf + aLane[m] + ks * 32, a[m][0], a[m][1], a[m][2], a[m][3]);
            uint32_t b[8][2];
            #pragma unroll
            for (int q = 0; q < 4; ++q)
                ldsm_x4(bbuf + bLane[q] + ks * 32,
                        b[2*q][0], b[2*q][1], b[2*q+1][0], b[2*q+1][1]);
            #pragma unroll
            for (int m = 0; m < 4; ++m)
                #pragma unroll
                for (int q = 0; q < 8; ++q)
                    mma_f16acc(acc[m][q], a[m], b[q]);
        }
        __syncthreads();
    }

    int r_base = warpM * 64 + (lane >> 2);
    int c_base = warpN * 64 + (lane & 3) * 2;

    if (bj == bi + 32) {
        #pragma unroll
        for (int m = 0; m < 4; ++m)
            #pragma unroll
            for (int q = 0; q < 8; ++q) {
                float2 lo = __half22float2(*(__half2*)&acc[m][q][0]);
                float2 hi = __half22float2(*(__half2*)&acc[m][q][1]);
                int rl0 = r_base + m * 16, cl = c_base + q * 8;
                if (rl0 == cl)         { g_pos[r0 + rl0] = lo.x;     g_pos[r0 + rl0 + NB] = lo.x; }
                if (rl0 == cl + 1)     { g_pos[r0 + rl0] = lo.y;     g_pos[r0 + rl0 + NB] = lo.y; }
                if (rl0 + 8 == cl)     { g_pos[r0 + rl0 + 8] = hi.x; g_pos[r0 + rl0 + 8 + NB] = hi.x; }
                if (rl0 + 8 == cl + 1) { g_pos[r0 + rl0 + 8] = hi.y; g_pos[r0 + rl0 + 8 + NB] = hi.y; }
            }
    }

    bool isDiag = (bi == bj);
    const __half2 cmulh = __float2half2_rn(EX2_SCALE);
    uint32_t cmul_u = *(const uint32_t*)&cmulh;

    uint32_t racc0[4], racc1[4], cacc[8];
    #pragma unroll
    for (int m = 0; m < 4; ++m) { racc0[m] = 0u; racc1[m] = 0u; }
    #pragma unroll
    for (int q = 0; q < 8; ++q) cacc[q] = 0u;

    #pragma unroll
    for (int m = 0; m < 4; ++m)
        #pragma unroll
        for (int q = 0; q < 8; ++q) {
            uint32_t e0u = h2ex2(h2mul(acc[m][q][0], cmul_u));
            uint32_t e1u = h2ex2(h2mul(acc[m][q][1], cmul_u));
            if (isDiag) {
                int rl0 = r_base + m * 16, cl = c_base + q * 8;
                if (rl0 == cl)         e0u &= 0xFFFF0000u;
                if (rl0 == cl + 1)     e0u &= 0x0000FFFFu;
                if (rl0 + 8 == cl)     e1u &= 0xFFFF0000u;
                if (rl0 + 8 == cl + 1) e1u &= 0x0000FFFFu;
            }
            racc0[m] = h2add(racc0[m], e0u);
            racc1[m] = h2add(racc1[m], e1u);
            cacc[q]  = h2add(cacc[q], h2add(e0u, e1u));
        }

    float* rowred = (float*)smem;                 // [128][2] by warpN
    float* colred = (float*)smem + 256;           // [128][2] by warpM

    #pragma unroll
    for (int m = 0; m < 4; ++m) {
        float2 f0 = __half22float2(*(__half2*)&racc0[m]);
        float2 f1 = __half22float2(*(__half2*)&racc1[m]);
        float a0 = f0.x + f0.y;
        float a1 = f1.x + f1.y;
        a0 += __shfl_xor_sync(0xffffffffu, a0, 1);
        a0 += __shfl_xor_sync(0xffffffffu, a0, 2);
        a1 += __shfl_xor_sync(0xffffffffu, a1, 1);
        a1 += __shfl_xor_sync(0xffffffffu, a1, 2);
        if ((lane & 3) == 0) {
            int row = warpM * 64 + m * 16 + (lane >> 2);
            rowred[row * 2 + warpN]       = a0;
            rowred[(row + 8) * 2 + warpN] = a1;
        }
    }

    if (!isDiag) {
        #pragma unroll
        for (int q = 0; q < 8; ++q) {
            float2 fc = __half22float2(*(__half2*)&cacc[q]);
            float a0 = fc.x, a1 = fc.y;
            a0 += __shfl_xor_sync(0xffffffffu, a0, 4);
            a0 += __shfl_xor_sync(0xffffffffu, a0, 8);
            a0 += __shfl_xor_sync(0xffffffffu, a0, 16);
            a1 += __shfl_xor_sync(0xffffffffu, a1, 4);
            a1 += __shfl_xor_sync(0xffffffffu, a1, 8);
            a1 += __shfl_xor_sync(0xffffffffu, a1, 16);
            if (lane < 4) {
                int n = warpN * 64 + q * 8 + lane * 2;
                colred[n * 2 + warpM]       = a0;
                colred[(n + 1) * 2 + warpM] = a1;
            }
        }
    }
    __syncthreads();

    g_partial[(size_t)bj * N2 + r0 + tid] = rowred[tid * 2] + rowred[tid * 2 + 1];
    if (!isDiag)
        g_partial[(size_t)bi * N2 + c0 + tid] = colred[tid * 2] + colred[tid * 2 + 1];
}

// ---------------------------------------------------------------------------
// Kernel 3: per-row loss + fused mean.
// ---------------------------------------------------------------------------
__global__ void k_rowloss(float* __restrict__ out) {
    __shared__ float st[8][68];
    __shared__ float sm[256];
    __shared__ int isLast;
    int tid = threadIdx.x;
    int r0  = blockIdx.x * 8;

    {
        int s  = tid >> 2;
        int ro = (tid & 3) * 2;
        float2 v = *(const float2*)&g_partial[(size_t)s * N2 + r0 + ro];
        st[ro][s]     = v.x;
        st[ro + 1][s] = v.y;
    }
    __syncthreads();

    int w    = tid >> 5;
    int lane = tid & 31;
    float S = st[w][lane] + st[w][lane + 32];
    #pragma unroll
    for (int o = 16; o > 0; o >>= 1) S += __shfl_xor_sync(0xffffffffu, S, o);

    if (lane == 0) {
        float ep = __expf(INV_TEMP * g_pos[r0 + w]);
        g_loss[r0 + w] = -logf(ep / (ep + S));
    }
    __threadfence();
    __syncthreads();
    if (tid == 0) {
        int old = atomicAdd(&g_sem, 1);
        isLast = (old == gridDim.x - 1);
    }
    __syncthreads();
    if (isLast) {
        float s = 0.f;
        #pragma unroll
        for (int i = 0; i < 8; ++i) {
            float4 v = *(const float4*)&g_loss[(tid + i * 256) * 4];
            s += v.x + v.y + v.z + v.w;
        }
        sm[tid] = s;
        __syncthreads();
        for (int stp = 128; stp > 0; stp >>= 1) {
            if (tid < stp) sm[tid] += sm[tid + stp];
            __syncthreads();
        }
        if (tid == 0) { out[0] = sm[0] * (1.0f / (float)N2); g_sem = 0; }
    }
}

extern "C" void kernel_launch(void* const* d_in, const int* in_sizes, int n_in,
                              void* d_out, int out_size) {
    const float* xi = (const float*)d_in[0];
    const float* xj = (const float*)d_in[1];
    float* out = (float*)d_out;

    cudaFuncSetAttribute(k_expsum_mma, cudaFuncAttributeMaxDynamicSharedMemorySize, SMEM_BYTES);

    k_normalize<<<256, 256>>>(xi, xj);
    k_expsum_mma<<<NTRI, 128, SMEM_BYTES>>>();
    k_rowloss<<<N2 / 8, 256>>>(out);
}

// round 16
// speedup vs baseline: 1.1322x; 1.0006x over previous
#include <cuda_runtime.h>
#include <cuda_fp16.h>
#include <cstdint>

#define NB 4096
#define N2 8192
#define DD 256
#define INV_TEMP 2.0f
#define EX2_SCALE 2.885390081777927f   // 2 * log2(e)

#define BM 128
#define BN 128
#define BK 64
#define NCHUNK (DD / BK)         // 4 k-chunks
#define NSTRIPE (N2 / BN)        // 64 column stripes
#define NTILE 64
#define NTRI (NTILE * (NTILE + 1) / 2)   // 2080
#define PADK 72                  // f16 elems per smem row (144B)

// Scratch (static device globals — no allocation)
__device__ __half         g_zh[(size_t)N2 * DD];            // normalized rows fp16
__device__ float          g_partial[(size_t)NSTRIPE * N2];  // [stripe][row]
__device__ float          g_pos[N2];
__device__ float          g_loss[N2];
__device__ int            g_sem;

__device__ __forceinline__ uint32_t smem_u32(const void* p) {
    return (uint32_t)__cvta_generic_to_shared(p);
}
__device__ __forceinline__ void ldsm_x4(uint32_t addr, uint32_t& r0, uint32_t& r1,
                                        uint32_t& r2, uint32_t& r3) {
    asm volatile("ldmatrix.sync.aligned.m8n8.x4.shared.b16 {%0,%1,%2,%3}, [%4];"
                 : "=r"(r0), "=r"(r1), "=r"(r2), "=r"(r3) : "r"(addr));
}
__device__ __forceinline__ void mma_f16acc(uint32_t* d, const uint32_t* a, const uint32_t* b) {
    asm volatile(
        "mma.sync.aligned.m16n8k16.row.col.f16.f16.f16.f16 "
        "{%0,%1}, {%2,%3,%4,%5}, {%6,%7}, {%0,%1};"
        : "+r"(d[0]), "+r"(d[1])
        : "r"(a[0]), "r"(a[1]), "r"(a[2]), "r"(a[3]), "r"(b[0]), "r"(b[1]));
}
__device__ __forceinline__ uint32_t h2ex2(uint32_t x) {
    uint32_t y;
    asm("ex2.approx.f16x2 %0, %1;" : "=r"(y) : "r"(x));
    return y;
}
__device__ __forceinline__ uint32_t h2mul(uint32_t a, uint32_t b) {
    __half2 r = __hmul2(*(__half2*)&a, *(__half2*)&b);
    return *(uint32_t*)&r;
}
__device__ __forceinline__ uint32_t h2add(uint32_t a, uint32_t b) {
    __half2 r = __hadd2(*(__half2*)&a, *(__half2*)&b);
    return *(uint32_t*)&r;
}
__device__ __forceinline__ void cp_async16(uint32_t smem_addr, const void* gptr) {
    asm volatile("cp.async.cg.shared.global [%0], [%1], 16;"
                 :: "r"(smem_addr), "l"(gptr) : "memory");
}
#define CP_COMMIT() asm volatile("cp.async.commit_group;" ::: "memory")
#define CP_WAIT(n)  asm volatile("cp.async.wait_group %0;" :: "n"(n) : "memory")

// ---------------------------------------------------------------------------
// Kernel 1: L2-normalize. One warp handles TWO pairs (4 rows).
// ---------------------------------------------------------------------------
__global__ void k_normalize(const float* __restrict__ xi, const float* __restrict__ xj) {
    int p    = blockIdx.x * 8 + (threadIdx.x >> 5);   // 0..2047
    int lane = threadIdx.x & 31;
    const float* s0 = xi + (size_t)p * DD;
    const float* s1 = xj + (size_t)p * DD;
    const float* s2 = xi + (size_t)(p + 2048) * DD;
    const float* s3 = xj + (size_t)(p + 2048) * DD;

    float4 v[4][2];
    v[0][0] = *(const float4*)(s0 + lane * 4);
    v[1][0] = *(const float4*)(s1 + lane * 4);
    v[2][0] = *(const float4*)(s2 + lane * 4);
    v[3][0] = *(const float4*)(s3 + lane * 4);
    v[0][1] = *(const float4*)(s0 + 128 + lane * 4);
    v[1][1] = *(const float4*)(s1 + 128 + lane * 4);
    v[2][1] = *(const float4*)(s2 + 128 + lane * 4);
    v[3][1] = *(const float4*)(s3 + 128 + lane * 4);

    float s[4];
    #pragma unroll
    for (int r = 0; r < 4; ++r) {
        float4 a = v[r][0], b = v[r][1];
        s[r] = a.x*a.x + a.y*a.y + a.z*a.z + a.w*a.w
             + b.x*b.x + b.y*b.y + b.z*b.z + b.w*b.w;
    }
    #pragma unroll
    for (int o = 16; o > 0; o >>= 1) {
        #pragma unroll
        for (int r = 0; r < 4; ++r)
            s[r] += __shfl_xor_sync(0xffffffffu, s[r], o);
    }
    int rows[4] = {p, p + NB, p + 2048, p + 2048 + NB};
    #pragma unroll
    for (int r = 0; r < 4; ++r) {
        float inv = 1.0f / fmaxf(sqrtf(s[r]), 1e-12f);
        float4 a = v[r][0], b = v[r][1];
        __half2 h[4];
        h[0] = __floats2half2_rn(a.x * inv, a.y * inv);
        h[1] = __floats2half2_rn(a.z * inv, a.w * inv);
        h[2] = __floats2half2_rn(b.x * inv, b.y * inv);
        h[3] = __floats2half2_rn(b.z * inv, b.w * inv);
        __half* d = g_zh + (size_t)rows[r] * DD;
        *(uint2*)(d + lane * 4)       = make_uint2(*(uint32_t*)&h[0], *(uint32_t*)&h[1]);
        *(uint2*)(d + 128 + lane * 4) = make_uint2(*(uint32_t*)&h[2], *(uint32_t*)&h[3]);
    }
}

// ---------------------------------------------------------------------------
// Kernel 2: f16-acc HMMA 128x128 tile, upper triangle, 4 warps x (64x64).
// Single-sync double-buffered mainloop: CP_WAIT; sync; prefetch; compute.
// ---------------------------------------------------------------------------
#define CHUNK_ELEMS (BM * PADK)
#define SMEM_BYTES  (2 * 2 * CHUNK_ELEMS * 2)   // 73728 B

__global__ __launch_bounds__(128, 3) void k_expsum_mma() {
    extern __shared__ __half smem[];
    int tid   = threadIdx.x;
    int lane  = tid & 31;
    int wid   = tid >> 5;
    int warpM = wid >> 1;
    int warpN = wid & 1;

    int idx = blockIdx.x;
    int bi = (int)(64.5f - sqrtf(64.5f * 64.5f - 2.0f * (float)idx));
    while ((bi + 1) * NTILE - ((bi + 1) * bi) / 2 <= idx) ++bi;
    while (bi * NTILE - (bi * (bi - 1)) / 2 > idx) --bi;
    int bj = bi + (idx - (bi * NTILE - (bi * (bi - 1)) / 2));
    int r0 = bi * BM;
    int c0 = bj * BN;

    int lrow = tid >> 3;
    int lcol = (tid & 7) * 8;
    uint32_t sbase = smem_u32(smem);

    auto load_chunk = [&](int kc, int b) {
        uint32_t aoff = sbase + (uint32_t)(b * 2 * CHUNK_ELEMS) * 2;
        uint32_t boff = aoff + (uint32_t)CHUNK_ELEMS * 2;
        const __half* gA = g_zh + (size_t)r0 * DD + kc * BK;
        const __half* gB = g_zh + (size_t)c0 * DD + kc * BK;
        #pragma unroll
        for (int i = 0; i < 8; ++i) {
            int row = lrow + i * 16;
            cp_async16(aoff + (uint32_t)(row * PADK + lcol) * 2,
                       gA + (size_t)row * DD + lcol);
            cp_async16(boff + (uint32_t)(row * PADK + lcol) * 2,
                       gB + (size_t)row * DD + lcol);
        }
        CP_COMMIT();
    };

    uint32_t aLane[4], bLane[4];
    {
        int arow_lane = lane & 15;
        int akh       = lane >> 4;
        #pragma unroll
        for (int m = 0; m < 4; ++m) {
            int row = warpM * 64 + m * 16 + arow_lane;
            aLane[m] = (uint32_t)(row * PADK + akh * 8) * 2;
        }
        int bn  = (lane & 7) | ((lane >> 4) << 3);
        int bkh = (lane >> 3) & 1;
        #pragma unroll
        for (int q = 0; q < 4; ++q) {
            int n = warpN * 64 + q * 16 + bn;
            bLane[q] = (uint32_t)(n * PADK + bkh * 8) * 2;
        }
    }

    uint32_t acc[4][8][2];
    #pragma unroll
    for (int m = 0; m < 4; ++m)
        #pragma unroll
        for (int q = 0; q < 8; ++q) { acc[m][q][0] = 0u; acc[m][q][1] = 0u; }

    load_chunk(0, 0);

    // Single-sync double-buffer: the top-of-iteration barrier both publishes
    // chunk kc's data AND guarantees compute(kc-1) finished reading the buffer
    // that load(kc+1) is about to overwrite.
    #pragma unroll
    for (int kc = 0; kc < NCHUNK; ++kc) {
        CP_WAIT(0);
        __syncthreads();
        if (kc + 1 < NCHUNK) load_chunk(kc + 1, (kc + 1) & 1);

        uint32_t abuf = sbase + (uint32_t)((kc & 1) * 2 * CHUNK_ELEMS) * 2;
        uint32_t bbuf = abuf + (uint32_t)CHUNK_ELEMS * 2;

        #pragma unroll
        for (int ks = 0; ks < BK / 16; ++ks) {
            uint32_t a[4][4];
            #pragma unroll
            for (int m = 0; m < 4; ++m)
                ldsm_x4(abuf + aLane[m] + ks * 32, a[m][0], a[m][1], a[m][2], a[m][3]);
            uint32_t b[8][2];
            #pragma unroll
            for (int q = 0; q < 4; ++q)
                ldsm_x4(bbuf + bLane[q] + ks * 32,
                        b[2*q][0], b[2*q][1], b[2*q+1][0], b[2*q+1][1]);
            #pragma unroll
            for (int m = 0; m < 4; ++m)
                #pragma unroll
                for (int q = 0; q < 8; ++q)
                    mma_f16acc(acc[m][q], a[m], b[q]);
        }
    }

    int r_base = warpM * 64 + (lane >> 2);
    int c_base = warpN * 64 + (lane & 3) * 2;

    if (bj == bi + 32) {
        #pragma unroll
        for (int m = 0; m < 4; ++m)
            #pragma unroll
            for (int q = 0; q < 8; ++q) {
                float2 lo = __half22float2(*(__half2*)&acc[m][q][0]);
                float2 hi = __half22float2(*(__half2*)&acc[m][q][1]);
                int rl0 = r_base + m * 16, cl = c_base + q * 8;
                if (rl0 == cl)         { g_pos[r0 + rl0] = lo.x;     g_pos[r0 + rl0 + NB] = lo.x; }
                if (rl0 == cl + 1)     { g_pos[r0 + rl0] = lo.y;     g_pos[r0 + rl0 + NB] = lo.y; }
                if (rl0 + 8 == cl)     { g_pos[r0 + rl0 + 8] = hi.x; g_pos[r0 + rl0 + 8 + NB] = hi.x; }
                if (rl0 + 8 == cl + 1) { g_pos[r0 + rl0 + 8] = hi.y; g_pos[r0 + rl0 + 8 + NB] = hi.y; }
            }
    }

    bool isDiag = (bi == bj);
    const __half2 cmulh = __float2half2_rn(EX2_SCALE);
    uint32_t cmul_u = *(const uint32_t*)&cmulh;

    uint32_t racc0[4], racc1[4], cacc[8];
    #pragma unroll
    for (int m = 0; m < 4; ++m) { racc0[m] = 0u; racc1[m] = 0u; }
    #pragma unroll
    for (int q = 0; q < 8; ++q) cacc[q] = 0u;

    #pragma unroll
    for (int m = 0; m < 4; ++m)
        #pragma unroll
        for (int q = 0; q < 8; ++q) {
            uint32_t e0u = h2ex2(h2mul(acc[m][q][0], cmul_u));
            uint32_t e1u = h2ex2(h2mul(acc[m][q][1], cmul_u));
            if (isDiag) {
                int rl0 = r_base + m * 16, cl = c_base + q * 8;
                if (rl0 == cl)         e0u &= 0xFFFF0000u;
                if (rl0 == cl + 1)     e0u &= 0x0000FFFFu;
                if (rl0 + 8 == cl)     e1u &= 0xFFFF0000u;
                if (rl0 + 8 == cl + 1) e1u &= 0x0000FFFFu;
            }
            racc0[m] = h2add(racc0[m], e0u);
            racc1[m] = h2add(racc1[m], e1u);
            cacc[q]  = h2add(cacc[q], h2add(e0u, e1u));
        }

    // Reduction scratch: first 4KB of buffer-0 region; compute(3) read only
    // buffer 1, and each slot is written by exactly one warp before the sync.
    float* rowred = (float*)smem;                 // [128][2] by warpN
    float* colred = (float*)smem + 256;           // [128][2] by warpM

    #pragma unroll
    for (int m = 0; m < 4; ++m) {
        float2 f0 = __half22float2(*(__half2*)&racc0[m]);
        float2 f1 = __half22float2(*(__half2*)&racc1[m]);
        float a0 = f0.x + f0.y;
        float a1 = f1.x + f1.y;
        a0 += __shfl_xor_sync(0xffffffffu, a0, 1);
        a0 += __shfl_xor_sync(0xffffffffu, a0, 2);
        a1 += __shfl_xor_sync(0xffffffffu, a1, 1);
        a1 += __shfl_xor_sync(0xffffffffu, a1, 2);
        if ((lane & 3) == 0) {
            int row = warpM * 64 + m * 16 + (lane >> 2);
            rowred[row * 2 + warpN]       = a0;
            rowred[(row + 8) * 2 + warpN] = a1;
        }
    }

    if (!isDiag) {
        #pragma unroll
        for (int q = 0; q < 8; ++q) {
            float2 fc = __half22float2(*(__half2*)&cacc[q]);
            float a0 = fc.x, a1 = fc.y;
            a0 += __shfl_xor_sync(0xffffffffu, a0, 4);
            a0 += __shfl_xor_sync(0xffffffffu, a0, 8);
            a0 += __shfl_xor_sync(0xffffffffu, a0, 16);
            a1 += __shfl_xor_sync(0xffffffffu, a1, 4);
            a1 += __shfl_xor_sync(0xffffffffu, a1, 8);
            a1 += __shfl_xor_sync(0xffffffffu, a1, 16);
            if (lane < 4) {
                int n = warpN * 64 + q * 8 + lane * 2;
                colred[n * 2 + warpM]       = a0;
                colred[(n + 1) * 2 + warpM] = a1;
            }
        }
    }
    __syncthreads();

    g_partial[(size_t)bj * N2 + r0 + tid] = rowred[tid * 2] + rowred[tid * 2 + 1];
    if (!isDiag)
        g_partial[(size_t)bi * N2 + c0 + tid] = colred[tid * 2] + colred[tid * 2 + 1];
}

// ---------------------------------------------------------------------------
// Kernel 3: per-row loss + fused mean.
// ---------------------------------------------------------------------------
__global__ void k_rowloss(float* __restrict__ out) {
    __shared__ float st[8][68];
    __shared__ float sm[256];
    __shared__ int isLast;
    int tid = threadIdx.x;
    int r0  = blockIdx.x * 8;

    {
        int s  = tid >> 2;
        int ro = (tid & 3) * 2;
        float2 v = *(const float2*)&g_partial[(size_t)s * N2 + r0 + ro];
        st[ro][s]     = v.x;
        st[ro + 1][s] = v.y;
    }
    __syncthreads();

    int w    = tid >> 5;
    int lane = tid & 31;
    float S = st[w][lane] + st[w][lane + 32];
    #pragma unroll
    for (int o = 16; o > 0; o >>= 1) S += __shfl_xor_sync(0xffffffffu, S, o);

    if (lane == 0) {
        float ep = __expf(INV_TEMP * g_pos[r0 + w]);
        g_loss[r0 + w] = -logf(ep / (ep + S));
    }
    __threadfence();
    __syncthreads();
    if (tid == 0) {
        int old = atomicAdd(&g_sem, 1);
        isLast = (old == gridDim.x - 1);
    }
    __syncthreads();
    if (isLast) {
        float s = 0.f;
        #pragma unroll
        for (int i = 0; i < 8; ++i) {
            float4 v = *(const float4*)&g_loss[(tid + i * 256) * 4];
            s += v.x + v.y + v.z + v.w;
        }
        sm[tid] = s;
        __syncthreads();
        for (int stp = 128; stp > 0; stp >>= 1) {
            if (tid < stp) sm[tid] += sm[tid + stp];
            __syncthreads();
        }
        if (tid == 0) { out[0] = sm[0] * (1.0f / (float)N2); g_sem = 0; }
    }
}

extern "C" void kernel_launch(void* const* d_in, const int* in_sizes, int n_in,
                              void* d_out, int out_size) {
    const float* xi = (const float*)d_in[0];
    const float* xj = (const float*)d_in[1];
    float* out = (float*)d_out;

    cudaFuncSetAttribute(k_expsum_mma, cudaFuncAttributeMaxDynamicSharedMemorySize, SMEM_BYTES);

    k_normalize<<<256, 256>>>(xi, xj);
    k_expsum_mma<<<NTRI, 128, SMEM_BYTES>>>();
    k_rowloss<<<N2 / 8, 256>>>(out);
}